// round 7
// baseline (speedup 1.0000x reference)
#include <cuda_runtime.h>

// InteractionArch: out[b] = concat(dense[b] (128),
//        triu(k=1) of Gram([dense[b]; sparse[b].reshape(26,128)]) (351))
// B=16384, D=128, F=26, OUTW=479.
//
// R4 skeleton (all 27 vectors resident, packed f32x2, natural triu order)
// + chunk-16 butterfly (R5-validated) to cut p[32]->p[16]:
//   v[27] packed               54 regs
//   p[16] chunk buffer         16 regs
//   misc                      ~30-40
// Cap 102 via __launch_bounds__(128,5) -> 20 warps/SM (was 16).
// No phasing, no streaming, no smem table (R5 lesson: mid-kernel dependent
// loads kill issue rate).

#define FF    26
#define NV    27
#define OUTW  479

typedef unsigned long long ull;

__device__ __forceinline__ ull mul2(ull a, ull b)
{
    ull d;
    asm("mul.rn.f32x2 %0, %1, %2;" : "=l"(d) : "l"(a), "l"(b));
    return d;
}
__device__ __forceinline__ ull fma2(ull a, ull b, ull c)
{
    ull d;
    asm("fma.rn.f32x2 %0, %1, %2, %3;" : "=l"(d) : "l"(a), "l"(b), "l"(c));
    return d;
}
__device__ __forceinline__ float hadd2(ull a)
{
    unsigned lo, hi;
    asm("mov.b64 {%0, %1}, %2;" : "=r"(lo), "=r"(hi) : "l"(a));
    return __uint_as_float(lo) + __uint_as_float(hi);
}

// dot over this lane's 4 dims: 2 packed MACs + horizontal add.
__device__ __forceinline__ float dotp(const ulonglong2 a, const ulonglong2 b)
{
    ull t = mul2(a.x, b.x);
    t = fma2(a.y, b.y, t);
    return hadd2(t);
}

// Reduce 16 lane-partial sums across 32 lanes; lane j ends holding the full
// sum of element (j>>1). 16 shuffles per 16 elements. (Validated in R5.)
__device__ __forceinline__ float bfly16(float (&p)[16], const int lane)
{
#pragma unroll
    for (int s = 0; s < 4; ++s) {
        const int m   = 16 >> s;   // partner distance 16,8,4,2
        const int cnt = 8 >> s;    // live elements halve 8,4,2,1
        const bool up = (lane & m) != 0;
#pragma unroll
        for (int i = 0; i < cnt; ++i) {
            float send = up ? p[i] : p[i + cnt];
            float recv = __shfl_xor_sync(0xffffffffu, send, m);
            float keep = up ? p[i + cnt] : p[i];
            p[i] = keep + recv;
        }
    }
    // Lanes j and j^1 hold partial sums of element j>>1; fold them.
    p[0] += __shfl_xor_sync(0xffffffffu, p[0], 1);
    return p[0];
}

__global__ __launch_bounds__(128, 5)
void interact_kernel(const float* __restrict__ dense,
                     const float* __restrict__ sparse,
                     float* __restrict__ out)
{
    const int gw   = (blockIdx.x * blockDim.x + threadIdx.x) >> 5;  // sample
    const int lane = threadIdx.x & 31;

    const ulonglong2* d2 = reinterpret_cast<const ulonglong2*>(dense)  + gw * 32;
    const ulonglong2* s2 = reinterpret_cast<const ulonglong2*>(sparse) + gw * (FF * 32);

    // All 27 vectors resident, packed: 54 registers.
    ulonglong2 v[NV];
    v[0] = d2[lane];
#pragma unroll
    for (int f = 0; f < FF; ++f)
        v[f + 1] = s2[f * 32 + lane];

    float* ob = out + (size_t)gw * OUTW;

    // Dense passthrough (row base only 4B-aligned -> scalar stores).
    {
        unsigned a, b, c, d;
        asm("mov.b64 {%0, %1}, %2;" : "=r"(a), "=r"(b) : "l"(v[0].x));
        asm("mov.b64 {%0, %1}, %2;" : "=r"(c), "=r"(d) : "l"(v[0].y));
        ob[lane * 4 + 0] = __uint_as_float(a);
        ob[lane * 4 + 1] = __uint_as_float(b);
        ob[lane * 4 + 2] = __uint_as_float(c);
        ob[lane * 4 + 3] = __uint_as_float(d);
    }

    float p[16];
    int slot  = 0;        // folded to constants by full unroll
    int obase = 128;      // natural triu order -> sequential chunks

#pragma unroll
    for (int f = 0; f < NV; ++f) {
#pragma unroll
        for (int g = f + 1; g < NV; ++g) {
            p[slot] = dotp(v[f], v[g]);
            ++slot;
            if (slot == 16) {
                float r = bfly16(p, lane);
                if ((lane & 1) == 0)
                    ob[obase + (lane >> 1)] = r;
                obase += 16;
                slot = 0;
            }
        }
    }

    // Tail chunk: 351 = 21*16 + 15 pairs; pad slot 15 with zero.
    p[15] = 0.0f;
    {
        float r = bfly16(p, lane);
        if ((lane & 1) == 0 && (lane >> 1) < 15)
            ob[obase + (lane >> 1)] = r;
    }
}

extern "C" void kernel_launch(void* const* d_in, const int* in_sizes, int n_in,
                              void* d_out, int out_size)
{
    const float* dense  = (const float*)d_in[0];
    const float* sparse = (const float*)d_in[1];
    float* out = (float*)d_out;

    // 16384 samples, 1 warp each, 4 warps/block -> 4096 blocks, 5 blocks/SM.
    interact_kernel<<<4096, 128>>>(dense, sparse, out);
}

// round 8
// speedup vs baseline: 1.6934x; 1.6934x over previous
#include <cuda_runtime.h>

// InteractionArch: out[b] = concat(dense[b] (128),
//        triu(k=1) of Gram([dense[b]; sparse[b].reshape(26,128)]) (351))
// B=16384, D=128, F=26, OUTW=479.
//
// R4 skeleton (all 27 vectors resident, packed f32x2, one warp per sample,
// natural triu order) + chunk-8 DOUBLE-BUFFERED butterfly:
//   - two 8-slot partial buffers alternate, so chunk c+1's independent dots
//     overlap chunk c's shuffle-reduction chain (breaks the WAR serialization
//     that held R4 at issue=57%)
//   - p shrinks 32 -> 16 regs; natural demand ~108 < cap 128 (no squeeze,
//     no spill; R2/R3/R6 all proved capping below demand is fatal)
// bfly8: 3 select-merge rounds (m=16,8,4) + 2 scalar folds (m=2,1);
// lane j ends with pair (j>>2); lanes with (lane&3)==0 store 8 consecutive
// floats -> coalesced 32B.

#define FF    26
#define NV    27
#define OUTW  479

typedef unsigned long long ull;

__device__ __forceinline__ ull mul2(ull a, ull b)
{
    ull d;
    asm("mul.rn.f32x2 %0, %1, %2;" : "=l"(d) : "l"(a), "l"(b));
    return d;
}
__device__ __forceinline__ ull fma2(ull a, ull b, ull c)
{
    ull d;
    asm("fma.rn.f32x2 %0, %1, %2, %3;" : "=l"(d) : "l"(a), "l"(b), "l"(c));
    return d;
}
__device__ __forceinline__ float hadd2(ull a)
{
    unsigned lo, hi;
    asm("mov.b64 {%0, %1}, %2;" : "=r"(lo), "=r"(hi) : "l"(a));
    return __uint_as_float(lo) + __uint_as_float(hi);
}

// dot over this lane's 4 dims: 2 packed MACs + horizontal add.
__device__ __forceinline__ float dotp(const ulonglong2 a, const ulonglong2 b)
{
    ull t = mul2(a.x, b.x);
    t = fma2(a.y, b.y, t);
    return hadd2(t);
}

// Reduce 8 lane-partial sums across 32 lanes; lane j ends holding the full
// sum of element (j>>2). Same merge pattern as the R5/R6-validated bfly16,
// one round shorter, plus two scalar folds.
__device__ __forceinline__ float bfly8(float (&p)[8], const int lane)
{
#pragma unroll
    for (int s = 0; s < 3; ++s) {
        const int m   = 16 >> s;   // partner distance 16,8,4
        const int cnt = 4 >> s;    // live elements 4,2,1
        const bool up = (lane & m) != 0;
#pragma unroll
        for (int i = 0; i < cnt; ++i) {
            float send = up ? p[i] : p[i + cnt];
            float recv = __shfl_xor_sync(0xffffffffu, send, m);
            float keep = up ? p[i + cnt] : p[i];
            p[i] = keep + recv;
        }
    }
    // Remaining partials live across lane bits 1,0.
    p[0] += __shfl_xor_sync(0xffffffffu, p[0], 2);
    p[0] += __shfl_xor_sync(0xffffffffu, p[0], 1);
    return p[0];
}

#define EMIT(val)                                                   \
    do {                                                            \
        pp[par][slot] = (val);                                      \
        ++slot;                                                     \
        if (slot == 8) {                                            \
            float r = bfly8(pp[par], lane);                         \
            if ((lane & 3) == 0)                                    \
                ob[obase + (lane >> 2)] = r;                        \
            obase += 8;                                             \
            par ^= 1;                                               \
            slot = 0;                                               \
        }                                                           \
    } while (0)

__global__ __launch_bounds__(128, 4)
void interact_kernel(const float* __restrict__ dense,
                     const float* __restrict__ sparse,
                     float* __restrict__ out)
{
    const int gw   = (blockIdx.x * blockDim.x + threadIdx.x) >> 5;  // sample
    const int lane = threadIdx.x & 31;

    const ulonglong2* d2 = reinterpret_cast<const ulonglong2*>(dense)  + gw * 32;
    const ulonglong2* s2 = reinterpret_cast<const ulonglong2*>(sparse) + gw * (FF * 32);

    // All 27 vectors resident, packed: 54 registers.
    ulonglong2 v[NV];
    v[0] = d2[lane];
#pragma unroll
    for (int f = 0; f < FF; ++f)
        v[f + 1] = s2[f * 32 + lane];

    float* ob = out + (size_t)gw * OUTW;

    // Dense passthrough (row base only 4B-aligned -> scalar stores).
    {
        unsigned a, b, c, d;
        asm("mov.b64 {%0, %1}, %2;" : "=r"(a), "=r"(b) : "l"(v[0].x));
        asm("mov.b64 {%0, %1}, %2;" : "=r"(c), "=r"(d) : "l"(v[0].y));
        ob[lane * 4 + 0] = __uint_as_float(a);
        ob[lane * 4 + 1] = __uint_as_float(b);
        ob[lane * 4 + 2] = __uint_as_float(c);
        ob[lane * 4 + 3] = __uint_as_float(d);
    }

    float pp[2][8];               // double-buffered chunk partials (16 regs)
    int slot  = 0;                // all three fold to constants under unroll
    int par   = 0;
    int obase = 128;              // natural triu order -> sequential chunks

#pragma unroll
    for (int f = 0; f < NV; ++f) {
#pragma unroll
        for (int g = f + 1; g < NV; ++g)
            EMIT(dotp(v[f], v[g]));
    }

    // Tail chunk: 351 = 43*8 + 7 pairs; pad slot 7 with zero.
    pp[par][7] = 0.0f;
    {
        float r = bfly8(pp[par], lane);
        if ((lane & 3) == 0 && (lane >> 2) < 7)
            ob[obase + (lane >> 2)] = r;
    }
}

extern "C" void kernel_launch(void* const* d_in, const int* in_sizes, int n_in,
                              void* d_out, int out_size)
{
    const float* dense  = (const float*)d_in[0];
    const float* sparse = (const float*)d_in[1];
    float* out = (float*)d_out;

    // 16384 samples, 1 warp each, 4 warps/block -> 4096 blocks, 4 blocks/SM.
    interact_kernel<<<4096, 128>>>(dense, sparse, out);
}

// round 11
// speedup vs baseline: 1.8463x; 1.0903x over previous
#include <cuda_runtime.h>
#include <cuda_bf16.h>
#include <mma.h>
#include <cstdint>

// InteractionArch via wmma/HMMA (base ISA, legal under .target sm_103):
// out[b] = concat(dense[b](128),
//                 triu(k=1) of Gram([dense[b]; sparse[b].reshape(26,128)]))
// B=16384, D=128, F=26, OUTW=479.
//
// One warp per sample. fp32 x split: hi = rn_bf16(x), lo = rn_bf16(x - hi).
// G = hi.hi^T + hi.lo^T + lo.hi^T  (lo.lo dropped, ~2^-18): THREE explicit
// wmma products per tile per k-step -- R9's [hi|lo] concatenation computed
// hi.hi^T + lo.lo^T and MISSED the cross terms (rel_err 6e-3).
// X staged in smem as 32 rows x [128 hi | 128 lo] bf16, ldm=280, rows 27-31
// zero. 3 output tiles ((0,0),(0,1),(1,1)) x 8 k-steps x 3 products = 72 mma.
// G written into the (dead) X smem region; lane f scatters triu row f.
// Fully warp-local: no __syncthreads.

#define FF   26
#define OUTW 479

#define LDM    280                        // bf16 elems/row (128 hi +128 lo +24 pad)
#define XW_B   (32 * LDM * 2)             // 17920 B per-warp X tile
#define G_LDM  36                         // f32 elems/row of G scratch
#define SM_TOTAL (4 * XW_B)               // 71680 B per CTA (4 warps)

using namespace nvcuda;

__global__ void __launch_bounds__(128)
interact_wmma(const float* __restrict__ dense,
              const float* __restrict__ sparse,
              float* __restrict__ out)
{
    extern __shared__ char smem[];

    const int tid  = threadIdx.x;
    const int wid  = tid >> 5;
    const int lane = tid & 31;
    const int s    = blockIdx.x * 4 + wid;          // sample id

    __nv_bfloat16* X  = reinterpret_cast<__nv_bfloat16*>(smem + wid * XW_B);
    float*         Gs = reinterpret_cast<float*>(smem + wid * XW_B);

    float* ob = out + (size_t)s * OUTW;

    // ---- Stage: 27 rows; lane covers cols 4*lane..4*lane+3 (float4) ----
#pragma unroll
    for (int r = 0; r < 27; ++r) {
        const float* src = (r == 0)
            ? dense  + (size_t)s * 128
            : sparse + (size_t)s * (FF * 128) + (size_t)(r - 1) * 128;
        const float4 x = reinterpret_cast<const float4*>(src)[lane];

        if (r == 0) {   // dense passthrough
            ob[lane * 4 + 0] = x.x;
            ob[lane * 4 + 1] = x.y;
            ob[lane * 4 + 2] = x.z;
            ob[lane * 4 + 3] = x.w;
        }

        // hi = rn_bf16(x)  (packed pairs; low half = first element)
        __nv_bfloat162 h01 = __floats2bfloat162_rn(x.x, x.y);
        __nv_bfloat162 h23 = __floats2bfloat162_rn(x.z, x.w);
        const uint32_t hw01 = reinterpret_cast<uint32_t&>(h01);
        const uint32_t hw23 = reinterpret_cast<uint32_t&>(h23);

        // lo = rn_bf16(x - hi); x - hi exact in fp32 (bf16 -> f32 is shift).
        const float l0 = x.x - __uint_as_float(hw01 << 16);
        const float l1 = x.y - __uint_as_float(hw01 & 0xFFFF0000u);
        const float l2 = x.z - __uint_as_float(hw23 << 16);
        const float l3 = x.w - __uint_as_float(hw23 & 0xFFFF0000u);
        __nv_bfloat162 p01 = __floats2bfloat162_rn(l0, l1);
        __nv_bfloat162 p23 = __floats2bfloat162_rn(l2, l3);

        const uint64_t hi64 = ((uint64_t)hw23 << 32) | hw01;
        const uint64_t lo64 = ((uint64_t)reinterpret_cast<uint32_t&>(p23) << 32)
                              | reinterpret_cast<uint32_t&>(p01);

        *reinterpret_cast<uint64_t*>(X + r * LDM +       4 * lane) = hi64;
        *reinterpret_cast<uint64_t*>(X + r * LDM + 128 + 4 * lane) = lo64;
    }
    // Zero rows 27..31, cols 0..255 (512B per row; 32 lanes x 16B).
#pragma unroll
    for (int r = 27; r < 32; ++r)
        reinterpret_cast<uint4*>(X + r * LDM)[lane] = make_uint4(0, 0, 0, 0);

    __syncwarp();

    // ---- Gram: G = hi.hi^T + hi.lo^T + lo.hi^T over K=128 (8 k-steps) ----
    wmma::fragment<wmma::accumulator, 16, 16, 16, float> c00, c01, c11;
    wmma::fill_fragment(c00, 0.0f);
    wmma::fill_fragment(c01, 0.0f);
    wmma::fill_fragment(c11, 0.0f);

#pragma unroll
    for (int k = 0; k < 8; ++k) {
        wmma::fragment<wmma::matrix_a, 16, 16, 16, __nv_bfloat16, wmma::row_major> a0h, a0l, a1h, a1l;
        wmma::fragment<wmma::matrix_b, 16, 16, 16, __nv_bfloat16, wmma::col_major> b0h, b0l, b1h, b1l;

        wmma::load_matrix_sync(a0h, X +                  k * 16, LDM);   // rows 0-15, hi
        wmma::load_matrix_sync(a0l, X +            128 + k * 16, LDM);   // rows 0-15, lo
        wmma::load_matrix_sync(a1h, X + 16 * LDM +       k * 16, LDM);   // rows 16-31, hi
        wmma::load_matrix_sync(a1l, X + 16 * LDM + 128 + k * 16, LDM);   // rows 16-31, lo
        wmma::load_matrix_sync(b0h, X +                  k * 16, LDM);   // cols(n) 0-15, hi
        wmma::load_matrix_sync(b0l, X +            128 + k * 16, LDM);   // cols(n) 0-15, lo
        wmma::load_matrix_sync(b1h, X + 16 * LDM +       k * 16, LDM);   // cols(n) 16-31, hi
        wmma::load_matrix_sync(b1l, X + 16 * LDM + 128 + k * 16, LDM);   // cols(n) 16-31, lo

        wmma::mma_sync(c00, a0h, b0h, c00);
        wmma::mma_sync(c00, a0h, b0l, c00);
        wmma::mma_sync(c00, a0l, b0h, c00);

        wmma::mma_sync(c01, a0h, b1h, c01);
        wmma::mma_sync(c01, a0h, b1l, c01);
        wmma::mma_sync(c01, a0l, b1h, c01);

        wmma::mma_sync(c11, a1h, b1h, c11);
        wmma::mma_sync(c11, a1h, b1l, c11);
        wmma::mma_sync(c11, a1l, b1h, c11);
    }

    // X is dead; reuse the region as the 32x36 f32 G scratch.
    __syncwarp();
    wmma::store_matrix_sync(Gs,                   c00, G_LDM, wmma::mem_row_major);
    wmma::store_matrix_sync(Gs + 16,              c01, G_LDM, wmma::mem_row_major);
    wmma::store_matrix_sync(Gs + 16 * G_LDM + 16, c11, G_LDM, wmma::mem_row_major);
    __syncwarp();

    // ---- Scatter triu: lane f emits (f, g) for g = f+1..26 ----
    const int f = lane;
    if (f < 26) {
        const int rb = 128 + f * 26 - (f * (f - 1)) / 2 - f - 1;
        for (int c = f + 1; c < 27; ++c)
            ob[rb + c] = Gs[f * G_LDM + c];
    }
}

extern "C" void kernel_launch(void* const* d_in, const int* in_sizes, int n_in,
                              void* d_out, int out_size)
{
    const float* dense  = (const float*)d_in[0];
    const float* sparse = (const float*)d_in[1];
    float* out = (float*)d_out;

    cudaFuncSetAttribute(interact_wmma,
                         cudaFuncAttributeMaxDynamicSharedMemorySize, SM_TOTAL);

    // 16384 samples / 4 per CTA -> 4096 CTAs of 128 threads; 3 CTAs/SM.
    interact_wmma<<<4096, 128, SM_TOTAL>>>(dense, sparse, out);
}